// round 14
// baseline (speedup 1.0000x reference)
#include <cuda_runtime.h>
#include <math.h>

// Problem constants
#define PB 8
#define PN 1025
#define PD 1024
#define PH 16
#define PDh 64
#define PM (PB*PN)      // 8200 rows
#define PEPS 1e-8f

// Scratch (device globals: allocation-free rule)
__device__ float g_h  [(size_t)PM * PD];    // rmsnorm output
__device__ float g_qkv[(size_t)PM * 3 * PD];// qkv (rope fused into epilogue)
__device__ float g_y  [(size_t)PM * PD];    // attention output
__device__ float g_sig[(size_t)PM * PD];    // sigmoid(gate) buffer

__device__ __forceinline__ float to_tf32(float x) {
    float r;
    asm("cvt.rna.tf32.f32 %0, %1;" : "=f"(r) : "f"(x));
    return r;
}

// cp.async helpers
__device__ __forceinline__ void cp_async16(void* smem_dst, const void* gmem_src, int src_bytes) {
    unsigned saddr = (unsigned)__cvta_generic_to_shared(smem_dst);
    asm volatile("cp.async.cg.shared.global [%0], [%1], 16, %2;\n"
                 :: "r"(saddr), "l"(gmem_src), "r"(src_bytes));
}
__device__ __forceinline__ void cp_commit() {
    asm volatile("cp.async.commit_group;\n" ::);
}
template<int N>
__device__ __forceinline__ void cp_wait() {
    asm volatile("cp.async.wait_group %0;\n" :: "n"(N));
}

#define MMA_TF32(c, a0,a1,a2,a3, b0,b1) \
    asm volatile("mma.sync.aligned.m16n8k8.row.col.f32.tf32.tf32.f32 " \
        "{%0,%1,%2,%3}, {%4,%5,%6,%7}, {%8,%9}, {%0,%1,%2,%3};" \
        : "+f"((c)[0]), "+f"((c)[1]), "+f"((c)[2]), "+f"((c)[3]) \
        : "r"(a0), "r"(a1), "r"(a2), "r"(a3), "r"(b0), "r"(b1))

// ---------------------------------------------------------------------------
// Kernel 1: zero-centered RMSNorm (unchanged, proven)
// ---------------------------------------------------------------------------
__global__ __launch_bounds__(256) void rmsnorm_kernel(
    const float* __restrict__ x, const float* __restrict__ g,
    float* __restrict__ h)
{
    __shared__ float sbuf[8];
    int row = blockIdx.x;
    const float* xr = x + (size_t)row * PD;
    int t = threadIdx.x;
    float v[4];
    float s = 0.f;
    #pragma unroll
    for (int i = 0; i < 4; i++) { v[i] = xr[i * 256 + t]; s += v[i]; }
    {
        int lane = t & 31, wid = t >> 5;
        #pragma unroll
        for (int o = 16; o > 0; o >>= 1) s += __shfl_xor_sync(0xffffffffu, s, o);
        if (lane == 0) sbuf[wid] = s;
        __syncthreads();
        s = 0.f;
        #pragma unroll
        for (int w = 0; w < 8; w++) s += sbuf[w];
    }
    float mean = s * (1.f / (float)PD);
    float s2 = 0.f;
    #pragma unroll
    for (int i = 0; i < 4; i++) { float c = v[i] - mean; s2 += c * c; }
    __syncthreads();
    {
        int lane = t & 31, wid = t >> 5;
        #pragma unroll
        for (int o = 16; o > 0; o >>= 1) s2 += __shfl_xor_sync(0xffffffffu, s2, o);
        if (lane == 0) sbuf[wid] = s2;
        __syncthreads();
        s2 = 0.f;
        #pragma unroll
        for (int w = 0; w < 8; w++) s2 += sbuf[w];
    }
    float scale = rsqrtf(s2 * (1.f / (float)PD) + PEPS);
    float* hr = h + (size_t)row * PD;
    #pragma unroll
    for (int i = 0; i < 4; i++)
        hr[i * 256 + t] = (v[i] - mean) * scale * g[i * 256 + t];
}

// ---------------------------------------------------------------------------
// tf32 GEMM body, RETILED for occupancy: 128x64 block tile, BK=16, 3-stage
// cp.async, 256 thr = 8 warps in 4(M) x 2(N), warp tile 32x32 (acc = 32 regs).
// EPI=0: C = acc + bias
// EPI=2: QKV + fused rope on cols < 2048
// EPI=3: final: C = xres + sig * (acc + bias)
// EPI=4: C = sigmoid(acc + bias)
// ---------------------------------------------------------------------------
#define SMS 20
#define GSTG 3
#define GEMM_SMEM ((GSTG * 128 * SMS + GSTG * 64 * SMS) * 4)   // 46080 B

template<int EPI>
__device__ __forceinline__ void gemm_body(
    char* smraw, int m0, int n0,
    const float* __restrict__ A, const float* __restrict__ W,
    const float* __restrict__ bias, float* __restrict__ C,
    int M, int Nc, int K,
    const float* __restrict__ xres, const float* __restrict__ sig,
    const float* __restrict__ fc)
{
    float* As = (float*)smraw;             // [GSTG][128][SMS]
    float* Bs = As + GSTG * 128 * SMS;     // [GSTG][64][SMS]

    int tid = threadIdx.x, lane = tid & 31, wid = tid >> 5;
    int wm = (wid & 3) * 32, wn = (wid >> 2) * 32;
    int gq = lane >> 2, gt = lane & 3;

    // A-load mapping: row lr (0..127), k-offset lk (0 or 8), two 16B each
    int lr = tid >> 1;
    int lk = (tid & 1) * 8;
    // B-load mapping: row br (0..63), 4-float col bc
    int br = tid >> 2;
    int bc = (tid & 3) * 4;

    float acc[2][4][4];
    #pragma unroll
    for (int mt = 0; mt < 2; mt++)
        #pragma unroll
        for (int nt = 0; nt < 4; nt++)
            #pragma unroll
            for (int c = 0; c < 4; c++) acc[mt][nt][c] = 0.f;

    bool aval = (m0 + lr) < M;
    int arow = aval ? (m0 + lr) : (M - 1);
    const float* Aptr = A + (size_t)arow * K + lk;
    const float* Wptr = W + (size_t)(n0 + br) * K + bc;
    int abytes = aval ? 16 : 0;

    const int steps = K >> 4;

    #pragma unroll
    for (int s = 0; s < GSTG - 1; s++) {
        int k0 = s * 16;
        cp_async16(&As[(s * 128 + lr) * SMS + lk],     Aptr + k0,     abytes);
        cp_async16(&As[(s * 128 + lr) * SMS + lk + 4], Aptr + k0 + 4, abytes);
        cp_async16(&Bs[(s * 64 + br) * SMS + bc],      Wptr + k0,     16);
        cp_commit();
    }

    for (int i = 0; i < steps; i++) {
        cp_wait<GSTG - 2>();
        __syncthreads();

        int pf = i + GSTG - 1;
        if (pf < steps) {
            int s = pf % GSTG;
            int k0 = pf * 16;
            cp_async16(&As[(s * 128 + lr) * SMS + lk],     Aptr + k0,     abytes);
            cp_async16(&As[(s * 128 + lr) * SMS + lk + 4], Aptr + k0 + 4, abytes);
            cp_async16(&Bs[(s * 64 + br) * SMS + bc],      Wptr + k0,     16);
        }
        cp_commit();

        const float* Asb = As + (i % GSTG) * 128 * SMS;
        const float* Bsb = Bs + (i % GSTG) * 64 * SMS;

        #pragma unroll
        for (int kk = 0; kk < 16; kk += 8) {
            unsigned af[2][4], bf[4][2];
            #pragma unroll
            for (int mt = 0; mt < 2; mt++) {
                int mm = wm + mt * 16 + gq;
                af[mt][0] = __float_as_uint(Asb[ mm      * SMS + kk + gt]);
                af[mt][1] = __float_as_uint(Asb[(mm + 8) * SMS + kk + gt]);
                af[mt][2] = __float_as_uint(Asb[ mm      * SMS + kk + gt + 4]);
                af[mt][3] = __float_as_uint(Asb[(mm + 8) * SMS + kk + gt + 4]);
            }
            #pragma unroll
            for (int nt = 0; nt < 4; nt++) {
                int nn = wn + nt * 8 + gq;
                bf[nt][0] = __float_as_uint(Bsb[nn * SMS + kk + gt]);
                bf[nt][1] = __float_as_uint(Bsb[nn * SMS + kk + gt + 4]);
            }
            #pragma unroll
            for (int mt = 0; mt < 2; mt++)
                #pragma unroll
                for (int nt = 0; nt < 4; nt++)
                    MMA_TF32(acc[mt][nt], af[mt][0], af[mt][1], af[mt][2], af[mt][3],
                             bf[nt][0], bf[nt][1]);
        }
    }

    #pragma unroll
    for (int mt = 0; mt < 2; mt++) {
        int r0 = m0 + wm + mt * 16 + gq;
        #pragma unroll
        for (int nt = 0; nt < 4; nt++) {
            int cb = n0 + wn + nt * 8 + gt * 2;
            float b0 = bias[cb], b1 = bias[cb + 1];
            #pragma unroll
            for (int hh = 0; hh < 2; hh++) {
                int r = r0 + hh * 8;
                if (r >= M) continue;
                size_t off = (size_t)r * Nc + cb;
                float v0 = acc[mt][nt][hh * 2 + 0] + b0;
                float v1 = acc[mt][nt][hh * 2 + 1] + b1;
                if (EPI == 0) {
                    C[off] = v0; C[off + 1] = v1;
                } else if (EPI == 2) {
                    if (cb < 2048) {
                        int n  = r % PN;
                        int d2 = (cb & 63) >> 1;
                        float2 f = *(const float2*)&fc[(size_t)(n * 32 + d2) * 2];
                        C[off]     = v0 * f.x - v1 * f.y;
                        C[off + 1] = v0 * f.y + v1 * f.x;
                    } else {
                        C[off] = v0; C[off + 1] = v1;
                    }
                } else if (EPI == 3) {
                    C[off]     = xres[off]     + sig[off]     * v0;
                    C[off + 1] = xres[off + 1] + sig[off + 1] * v1;
                } else {  // EPI == 4
                    C[off]     = 1.f / (1.f + __expf(-v0));
                    C[off + 1] = 1.f / (1.f + __expf(-v1));
                }
            }
        }
    }
}

template<int EPI>
__global__ __launch_bounds__(256, 3) void mma_nt(
    const float* __restrict__ A, const float* __restrict__ W,
    const float* __restrict__ bias, float* __restrict__ C,
    int M, int Nc, int K,
    const float* __restrict__ xres, const float* __restrict__ sig,
    const float* __restrict__ fc)
{
    extern __shared__ char smraw[];
    gemm_body<EPI>(smraw, blockIdx.y * 128, blockIdx.x * 64,
                   A, W, bias, C, M, Nc, K, xres, sig, fc);
}

// ---------------------------------------------------------------------------
// Flash attention body (R7-proven, unchanged)
// ---------------------------------------------------------------------------
#define KS_STR 68
#define VS_STR 72
#define PS_STR 68
#define NKT ((PN + 63) / 64)
#define FLASH_SMEM ((2*64*KS_STR + 2*64*VS_STR + 128*PS_STR) * 4)   // 106496

__device__ __forceinline__ void flash_body(
    float* sm, const float* __restrict__ qkv, const float* __restrict__ Bbias,
    float* __restrict__ y, int b, int h, int q0)
{
    float* Ks = sm;
    float* Vs = sm + 2 * 64 * KS_STR;
    float* Ps = sm + 2 * 64 * KS_STR + 2 * 64 * VS_STR;

    int tid = threadIdx.x, lane = tid & 31, wid = tid >> 5;
    int gq = lane >> 2, gt = lane & 3;

    int wrow = wid * 16;
    int r1 = q0 + wrow + gq;
    int r2 = r1 + 8;
    bool r1ok = r1 < PN, r2ok = r2 < PN;

    const float* qkv_bh = qkv + ((size_t)b * PN) * 3072 + h * 64;

    {
        for (int i = tid; i < 64 * 16; i += 256) {
            int kr = i >> 4, dg = (i & 15) << 2;
            int gk = kr;
            int ok = (gk < PN) ? 16 : 0;
            const float* base = qkv_bh + (size_t)((gk < PN) ? gk : (PN - 1)) * 3072 + dg;
            cp_async16(&Ks[kr * KS_STR + dg], base + 1024, ok);
            cp_async16(&Vs[kr * VS_STR + dg], base + 2048, ok);
        }
        cp_commit();
    }

    unsigned qf[8][4];
    {
        const float* q1 = qkv_bh + (size_t)(r1ok ? r1 : 0) * 3072;
        const float* q2 = qkv_bh + (size_t)(r2ok ? r2 : 0) * 3072;
        #pragma unroll
        for (int ks = 0; ks < 8; ks++) {
            int c0 = ks * 8 + gt, c1 = c0 + 4;
            qf[ks][0] = r1ok ? __float_as_uint(to_tf32(__ldg(q1 + c0) * 0.125f)) : 0u;
            qf[ks][1] = r2ok ? __float_as_uint(to_tf32(__ldg(q2 + c0) * 0.125f)) : 0u;
            qf[ks][2] = r1ok ? __float_as_uint(to_tf32(__ldg(q1 + c1) * 0.125f)) : 0u;
            qf[ks][3] = r2ok ? __float_as_uint(to_tf32(__ldg(q2 + c1) * 0.125f)) : 0u;
        }
    }

    float oacc[8][4];
    #pragma unroll
    for (int nt = 0; nt < 8; nt++)
        #pragma unroll
        for (int c = 0; c < 4; c++) oacc[nt][c] = 0.f;
    float m1 = -1e30f, m2 = -1e30f, l1 = 0.f, l2 = 0.f;

    const float* bb1 = Bbias + (size_t)(r1ok ? r1 : 0) * PN;
    const float* bb2 = Bbias + (size_t)(r2ok ? r2 : 0) * PN;

    for (int it = 0; it < NKT; it++) {
        int k0 = it * 64;
        cp_wait<0>();
        __syncthreads();

        if (it + 1 < NKT) {
            int s = (it + 1) & 1;
            int nk0 = (it + 1) * 64;
            for (int i = tid; i < 64 * 16; i += 256) {
                int kr = i >> 4, dg = (i & 15) << 2;
                int gk = nk0 + kr;
                int ok = (gk < PN) ? 16 : 0;
                const float* base = qkv_bh + (size_t)((gk < PN) ? gk : (PN - 1)) * 3072 + dg;
                cp_async16(&Ks[(s * 64 + kr) * KS_STR + dg], base + 1024, ok);
                cp_async16(&Vs[(s * 64 + kr) * VS_STR + dg], base + 2048, ok);
            }
        }
        cp_commit();

        const float* Ksb = Ks + (it & 1) * 64 * KS_STR;
        const float* Vsb = Vs + (it & 1) * 64 * VS_STR;

        float sacc[8][4];
        #pragma unroll
        for (int nt = 0; nt < 8; nt++)
            #pragma unroll
            for (int c = 0; c < 4; c++) sacc[nt][c] = 0.f;

        #pragma unroll
        for (int ks = 0; ks < 8; ks++) {
            int kk = ks * 8;
            #pragma unroll
            for (int nt = 0; nt < 8; nt++) {
                unsigned b0 = __float_as_uint(to_tf32(Ksb[(nt * 8 + gq) * KS_STR + kk + gt]));
                unsigned b1 = __float_as_uint(to_tf32(Ksb[(nt * 8 + gq) * KS_STR + kk + gt + 4]));
                MMA_TF32(sacc[nt], qf[ks][0], qf[ks][1], qf[ks][2], qf[ks][3], b0, b1);
            }
        }

        float mx1 = -1e30f, mx2 = -1e30f;
        #pragma unroll
        for (int nt = 0; nt < 8; nt++) {
            int gc0 = k0 + nt * 8 + gt * 2;
            int gc1 = gc0 + 1;
            bool c0ok = gc0 < PN, c1ok = gc1 < PN;
            sacc[nt][0] = (r1ok && c0ok) ? sacc[nt][0] + __ldg(bb1 + gc0) : -1e30f;
            sacc[nt][1] = (r1ok && c1ok) ? sacc[nt][1] + __ldg(bb1 + gc1) : -1e30f;
            sacc[nt][2] = (r2ok && c0ok) ? sacc[nt][2] + __ldg(bb2 + gc0) : -1e30f;
            sacc[nt][3] = (r2ok && c1ok) ? sacc[nt][3] + __ldg(bb2 + gc1) : -1e30f;
            mx1 = fmaxf(mx1, fmaxf(sacc[nt][0], sacc[nt][1]));
            mx2 = fmaxf(mx2, fmaxf(sacc[nt][2], sacc[nt][3]));
        }
        mx1 = fmaxf(mx1, __shfl_xor_sync(0xffffffffu, mx1, 1));
        mx1 = fmaxf(mx1, __shfl_xor_sync(0xffffffffu, mx1, 2));
        mx2 = fmaxf(mx2, __shfl_xor_sync(0xffffffffu, mx2, 1));
        mx2 = fmaxf(mx2, __shfl_xor_sync(0xffffffffu, mx2, 2));

        float mn1 = fmaxf(m1, mx1), mn2 = fmaxf(m2, mx2);
        float corr1 = __expf(m1 - mn1), corr2 = __expf(m2 - mn2);
        m1 = mn1; m2 = mn2;

        float sum1 = 0.f, sum2 = 0.f;
        #pragma unroll
        for (int nt = 0; nt < 8; nt++) {
            float p0 = __expf(sacc[nt][0] - m1);
            float p1 = __expf(sacc[nt][1] - m1);
            float p2 = __expf(sacc[nt][2] - m2);
            float p3 = __expf(sacc[nt][3] - m2);
            sum1 += p0 + p1; sum2 += p2 + p3;
            int col = nt * 8 + gt * 2;
            *(float2*)&Ps[(wrow + gq)     * PS_STR + col] = make_float2(to_tf32(p0), to_tf32(p1));
            *(float2*)&Ps[(wrow + gq + 8) * PS_STR + col] = make_float2(to_tf32(p2), to_tf32(p3));
        }
        sum1 += __shfl_xor_sync(0xffffffffu, sum1, 1);
        sum1 += __shfl_xor_sync(0xffffffffu, sum1, 2);
        sum2 += __shfl_xor_sync(0xffffffffu, sum2, 1);
        sum2 += __shfl_xor_sync(0xffffffffu, sum2, 2);
        l1 = l1 * corr1 + sum1;
        l2 = l2 * corr2 + sum2;

        #pragma unroll
        for (int nt = 0; nt < 8; nt++) {
            oacc[nt][0] *= corr1; oacc[nt][1] *= corr1;
            oacc[nt][2] *= corr2; oacc[nt][3] *= corr2;
        }
        __syncwarp();

        #pragma unroll
        for (int ks = 0; ks < 8; ks++) {
            int kk = ks * 8;
            unsigned a0 = __float_as_uint(Ps[(wrow + gq)     * PS_STR + kk + gt]);
            unsigned a1 = __float_as_uint(Ps[(wrow + gq + 8) * PS_STR + kk + gt]);
            unsigned a2 = __float_as_uint(Ps[(wrow + gq)     * PS_STR + kk + gt + 4]);
            unsigned a3 = __float_as_uint(Ps[(wrow + gq + 8) * PS_STR + kk + gt + 4]);
            #pragma unroll
            for (int nt = 0; nt < 8; nt++) {
                unsigned b0 = __float_as_uint(to_tf32(Vsb[(kk + gt)     * VS_STR + nt * 8 + gq]));
                unsigned b1 = __float_as_uint(to_tf32(Vsb[(kk + gt + 4) * VS_STR + nt * 8 + gq]));
                MMA_TF32(oacc[nt], a0, a1, a2, a3, b0, b1);
            }
        }
    }

    float inv1 = 1.f / l1, inv2 = 1.f / l2;
    #pragma unroll
    for (int nt = 0; nt < 8; nt++) {
        int col = h * 64 + nt * 8 + gt * 2;
        if (r1ok) {
            float* dst = y + ((size_t)(b * PN + r1)) * PD + col;
            dst[0] = oacc[nt][0] * inv1;
            dst[1] = oacc[nt][1] * inv1;
        }
        if (r2ok) {
            float* dst = y + ((size_t)(b * PN + r2)) * PD + col;
            dst[0] = oacc[nt][2] * inv2;
            dst[1] = oacc[nt][3] * inv2;
        }
    }
}

// ---------------------------------------------------------------------------
// Combined kernel: blocks [0,1152) = flash; rest = gate GEMM (128x64 tiles)
// ---------------------------------------------------------------------------
#define FLASH_BLOCKS (((PN + 127) / 128) * PH * PB)    // 1152
#define GATE_NX (PD / 64)                              // 16
#define GATE_BLOCKS (GATE_NX * ((PM + 127) / 128))     // 16*65 = 1040

__global__ __launch_bounds__(256, 2) void flash_gate_kernel(
    const float* __restrict__ qkv, const float* __restrict__ Bbias,
    float* __restrict__ y,
    const float* __restrict__ h, const float* __restrict__ gate_w,
    const float* __restrict__ gate_b, float* __restrict__ sig)
{
    extern __shared__ char smraw[];
    int bid = blockIdx.x;
    if (bid < FLASH_BLOCKS) {
        int qt = bid % 9;
        int hh = (bid / 9) % PH;
        int bb = bid / (9 * PH);
        flash_body((float*)smraw, qkv, Bbias, y, bb, hh, qt * 128);
    } else {
        int gid = bid - FLASH_BLOCKS;
        int n0 = (gid % GATE_NX) * 64;
        int m0 = (gid / GATE_NX) * 128;
        gemm_body<4>(smraw, m0, n0, h, gate_w, gate_b, sig,
                     PM, PD, PD, nullptr, nullptr, nullptr);
    }
}

// ---------------------------------------------------------------------------
// Launch
// ---------------------------------------------------------------------------
extern "C" void kernel_launch(void* const* d_in, const int* in_sizes, int n_in,
                              void* d_out, int out_size)
{
    (void)in_sizes; (void)n_in; (void)out_size;
    const float* x      = (const float*)d_in[0];
    const float* fc     = (const float*)d_in[1];
    const float* g      = (const float*)d_in[2];
    const float* qkv_w  = (const float*)d_in[3];
    const float* qkv_b  = (const float*)d_in[4];
    const float* out_w  = (const float*)d_in[5];
    const float* out_b  = (const float*)d_in[6];
    const float* gate_w = (const float*)d_in[7];
    const float* gate_b = (const float*)d_in[8];
    const float* Bbias  = (const float*)d_in[9];
    float* out = (float*)d_out;

    float *h, *qkv, *y, *sig;
    cudaGetSymbolAddress((void**)&h,   g_h);
    cudaGetSymbolAddress((void**)&qkv, g_qkv);
    cudaGetSymbolAddress((void**)&y,   g_y);
    cudaGetSymbolAddress((void**)&sig, g_sig);

    cudaFuncSetAttribute(mma_nt<2>, cudaFuncAttributeMaxDynamicSharedMemorySize, GEMM_SMEM);
    cudaFuncSetAttribute(mma_nt<3>, cudaFuncAttributeMaxDynamicSharedMemorySize, GEMM_SMEM);
    cudaFuncSetAttribute(flash_gate_kernel,
                         cudaFuncAttributeMaxDynamicSharedMemorySize, FLASH_SMEM);

    // 1. zero-centered RMSNorm (fp32)
    rmsnorm_kernel<<<PM, 256>>>(x, g, h);

    // 2. QKV projection with fused RoPE epilogue (128x64 tiles)
    dim3 g1(3072 / 64, (PM + 127) / 128);
    mma_nt<2><<<g1, 256, GEMM_SMEM>>>(h, qkv_w, qkv_b, qkv, PM, 3072, PD,
                                      nullptr, nullptr, fc);

    // 3. flash attention + gate GEMM fused into one launch (overlap)
    flash_gate_kernel<<<FLASH_BLOCKS + GATE_BLOCKS, 256, FLASH_SMEM>>>(
        qkv, Bbias, y, h, gate_w, gate_b, sig);

    // 4. out projection with final fused epilogue:
    //    out = x + sig * (y @ out_w^T + out_b)
    dim3 g2(PD / 64, (PM + 127) / 128);
    mma_nt<3><<<g2, 256, GEMM_SMEM>>>(y, out_w, out_b, out, PM, PD, PD,
                                      x, sig, nullptr);
}

// round 16
// speedup vs baseline: 1.1057x; 1.1057x over previous
#include <cuda_runtime.h>
#include <math.h>

// Problem constants
#define PB 8
#define PN 1025
#define PD 1024
#define PH 16
#define PDh 64
#define PM (PB*PN)      // 8200 rows
#define PEPS 1e-8f

// Scratch (device globals: allocation-free rule)
__device__ float g_h  [(size_t)PM * PD];    // rmsnorm output
__device__ float g_qkv[(size_t)PM * 3 * PD];// qkv (rope fused into epilogue)
__device__ float g_y  [(size_t)PM * PD];    // attention output
__device__ float g_sig[(size_t)PM * PD];    // sigmoid(gate) buffer

__device__ __forceinline__ float to_tf32(float x) {
    float r;
    asm("cvt.rna.tf32.f32 %0, %1;" : "=f"(r) : "f"(x));
    return r;
}

// cp.async helpers
__device__ __forceinline__ void cp_async16(void* smem_dst, const void* gmem_src, int src_bytes) {
    unsigned saddr = (unsigned)__cvta_generic_to_shared(smem_dst);
    asm volatile("cp.async.cg.shared.global [%0], [%1], 16, %2;\n"
                 :: "r"(saddr), "l"(gmem_src), "r"(src_bytes));
}
__device__ __forceinline__ void cp_commit() {
    asm volatile("cp.async.commit_group;\n" ::);
}
template<int N>
__device__ __forceinline__ void cp_wait() {
    asm volatile("cp.async.wait_group %0;\n" :: "n"(N));
}

#define MMA_TF32(c, a0,a1,a2,a3, b0,b1) \
    asm volatile("mma.sync.aligned.m16n8k8.row.col.f32.tf32.tf32.f32 " \
        "{%0,%1,%2,%3}, {%4,%5,%6,%7}, {%8,%9}, {%0,%1,%2,%3};" \
        : "+f"((c)[0]), "+f"((c)[1]), "+f"((c)[2]), "+f"((c)[3]) \
        : "r"(a0), "r"(a1), "r"(a2), "r"(a3), "r"(b0), "r"(b1))

// ---------------------------------------------------------------------------
// Kernel 1: zero-centered RMSNorm (unchanged, proven)
// ---------------------------------------------------------------------------
__global__ __launch_bounds__(256) void rmsnorm_kernel(
    const float* __restrict__ x, const float* __restrict__ g,
    float* __restrict__ h)
{
    __shared__ float sbuf[8];
    int row = blockIdx.x;
    const float* xr = x + (size_t)row * PD;
    int t = threadIdx.x;
    float v[4];
    float s = 0.f;
    #pragma unroll
    for (int i = 0; i < 4; i++) { v[i] = xr[i * 256 + t]; s += v[i]; }
    {
        int lane = t & 31, wid = t >> 5;
        #pragma unroll
        for (int o = 16; o > 0; o >>= 1) s += __shfl_xor_sync(0xffffffffu, s, o);
        if (lane == 0) sbuf[wid] = s;
        __syncthreads();
        s = 0.f;
        #pragma unroll
        for (int w = 0; w < 8; w++) s += sbuf[w];
    }
    float mean = s * (1.f / (float)PD);
    float s2 = 0.f;
    #pragma unroll
    for (int i = 0; i < 4; i++) { float c = v[i] - mean; s2 += c * c; }
    __syncthreads();
    {
        int lane = t & 31, wid = t >> 5;
        #pragma unroll
        for (int o = 16; o > 0; o >>= 1) s2 += __shfl_xor_sync(0xffffffffu, s2, o);
        if (lane == 0) sbuf[wid] = s2;
        __syncthreads();
        s2 = 0.f;
        #pragma unroll
        for (int w = 0; w < 8; w++) s2 += sbuf[w];
    }
    float scale = rsqrtf(s2 * (1.f / (float)PD) + PEPS);
    float* hr = h + (size_t)row * PD;
    #pragma unroll
    for (int i = 0; i < 4; i++)
        hr[i * 256 + t] = (v[i] - mean) * scale * g[i * 256 + t];
}

// ---------------------------------------------------------------------------
// tf32 GEMM body — R12 configuration (proven best): 128x128 block tile,
// BK=16, 3-stage cp.async, 8 warps x (64x32).
// EPI=0: C = acc + bias
// EPI=2: QKV + fused rope on cols < 2048
// EPI=3: final: C = xres + sig * (acc + bias)
// EPI=4: C = sigmoid(acc + bias)
// ---------------------------------------------------------------------------
#define SMS 20
#define GSTG 3
#define GEMM_SMEM (GSTG * 128 * SMS * 2 * 4)   // 61440 B

template<int EPI>
__device__ __forceinline__ void gemm_body(
    char* smraw, int m0, int n0,
    const float* __restrict__ A, const float* __restrict__ W,
    const float* __restrict__ bias, float* __restrict__ C,
    int M, int Nc, int K,
    const float* __restrict__ xres, const float* __restrict__ sig,
    const float* __restrict__ fc)
{
    float* As = (float*)smraw;             // [GSTG][128][SMS]
    float* Bs = As + GSTG * 128 * SMS;

    int tid = threadIdx.x, lane = tid & 31, wid = tid >> 5;
    int wm = (wid & 1) * 64, wn = (wid >> 1) * 32;

    int lr = tid >> 1;
    int lk = (tid & 1) * 8;
    int gq = lane >> 2, gt = lane & 3;

    float acc[4][4][4];
    #pragma unroll
    for (int mt = 0; mt < 4; mt++)
        #pragma unroll
        for (int nt = 0; nt < 4; nt++)
            #pragma unroll
            for (int c = 0; c < 4; c++) acc[mt][nt][c] = 0.f;

    bool aval = (m0 + lr) < M;
    int arow = aval ? (m0 + lr) : (M - 1);
    const float* Aptr = A + (size_t)arow * K + lk;
    const float* Wptr = W + (size_t)(n0 + lr) * K + lk;
    int abytes = aval ? 16 : 0;

    const int steps = K >> 4;

    #pragma unroll
    for (int s = 0; s < GSTG - 1; s++) {
        int k0 = s * 16;
        cp_async16(&As[(s * 128 + lr) * SMS + lk],     Aptr + k0,     abytes);
        cp_async16(&As[(s * 128 + lr) * SMS + lk + 4], Aptr + k0 + 4, abytes);
        cp_async16(&Bs[(s * 128 + lr) * SMS + lk],     Wptr + k0,     16);
        cp_async16(&Bs[(s * 128 + lr) * SMS + lk + 4], Wptr + k0 + 4, 16);
        cp_commit();
    }

    for (int i = 0; i < steps; i++) {
        cp_wait<GSTG - 2>();
        __syncthreads();

        int pf = i + GSTG - 1;
        if (pf < steps) {
            int s = pf % GSTG;
            int k0 = pf * 16;
            cp_async16(&As[(s * 128 + lr) * SMS + lk],     Aptr + k0,     abytes);
            cp_async16(&As[(s * 128 + lr) * SMS + lk + 4], Aptr + k0 + 4, abytes);
            cp_async16(&Bs[(s * 128 + lr) * SMS + lk],     Wptr + k0,     16);
            cp_async16(&Bs[(s * 128 + lr) * SMS + lk + 4], Wptr + k0 + 4, 16);
        }
        cp_commit();

        const float* Asb = As + (i % GSTG) * 128 * SMS;
        const float* Bsb = Bs + (i % GSTG) * 128 * SMS;

        #pragma unroll
        for (int kk = 0; kk < 16; kk += 8) {
            unsigned af[4][4], bf[4][2];
            #pragma unroll
            for (int mt = 0; mt < 4; mt++) {
                int mm = wm + mt * 16 + gq;
                af[mt][0] = __float_as_uint(Asb[ mm      * SMS + kk + gt]);
                af[mt][1] = __float_as_uint(Asb[(mm + 8) * SMS + kk + gt]);
                af[mt][2] = __float_as_uint(Asb[ mm      * SMS + kk + gt + 4]);
                af[mt][3] = __float_as_uint(Asb[(mm + 8) * SMS + kk + gt + 4]);
            }
            #pragma unroll
            for (int nt = 0; nt < 4; nt++) {
                int nn = wn + nt * 8 + gq;
                bf[nt][0] = __float_as_uint(Bsb[nn * SMS + kk + gt]);
                bf[nt][1] = __float_as_uint(Bsb[nn * SMS + kk + gt + 4]);
            }
            #pragma unroll
            for (int mt = 0; mt < 4; mt++)
                #pragma unroll
                for (int nt = 0; nt < 4; nt++)
                    MMA_TF32(acc[mt][nt], af[mt][0], af[mt][1], af[mt][2], af[mt][3],
                             bf[nt][0], bf[nt][1]);
        }
    }

    #pragma unroll
    for (int mt = 0; mt < 4; mt++) {
        int r0 = m0 + wm + mt * 16 + gq;
        #pragma unroll
        for (int nt = 0; nt < 4; nt++) {
            int cb = n0 + wn + nt * 8 + gt * 2;
            float b0 = bias[cb], b1 = bias[cb + 1];
            #pragma unroll
            for (int hh = 0; hh < 2; hh++) {
                int r = r0 + hh * 8;
                if (r >= M) continue;
                size_t off = (size_t)r * Nc + cb;
                float v0 = acc[mt][nt][hh * 2 + 0] + b0;
                float v1 = acc[mt][nt][hh * 2 + 1] + b1;
                if (EPI == 0) {
                    C[off] = v0; C[off + 1] = v1;
                } else if (EPI == 2) {
                    if (cb < 2048) {
                        int n  = r % PN;
                        int d2 = (cb & 63) >> 1;
                        float2 f = *(const float2*)&fc[(size_t)(n * 32 + d2) * 2];
                        C[off]     = v0 * f.x - v1 * f.y;
                        C[off + 1] = v0 * f.y + v1 * f.x;
                    } else {
                        C[off] = v0; C[off + 1] = v1;
                    }
                } else if (EPI == 3) {
                    C[off]     = xres[off]     + sig[off]     * v0;
                    C[off + 1] = xres[off + 1] + sig[off + 1] * v1;
                } else {  // EPI == 4
                    C[off]     = 1.f / (1.f + __expf(-v0));
                    C[off + 1] = 1.f / (1.f + __expf(-v1));
                }
            }
        }
    }
}

template<int EPI>
__global__ __launch_bounds__(256, 2) void mma_nt(
    const float* __restrict__ A, const float* __restrict__ W,
    const float* __restrict__ bias, float* __restrict__ C,
    int M, int Nc, int K,
    const float* __restrict__ xres, const float* __restrict__ sig,
    const float* __restrict__ fc)
{
    extern __shared__ char smraw[];
    gemm_body<EPI>(smraw, blockIdx.y * 128, blockIdx.x * 128,
                   A, W, bias, C, M, Nc, K, xres, sig, fc);
}

// ---------------------------------------------------------------------------
// Flash attention body: tf32 m16n8k8, q-tile 128, k-tile 64, double-buffered
// cp.async K/V, one __syncthreads per tile. Raw fp32 bits as tf32 operands
// (HW truncation, R7 semantics). Scalar __ldg bias loads (alignment-safe).
// ---------------------------------------------------------------------------
#define KS_STR 68
#define VS_STR 72
#define PS_STR 68
#define NKT ((PN + 63) / 64)
#define FLASH_SMEM ((2*64*KS_STR + 2*64*VS_STR + 128*PS_STR) * 4)   // 106496

__device__ __forceinline__ void flash_body(
    float* sm, const float* __restrict__ qkv, const float* __restrict__ Bbias,
    float* __restrict__ y, int b, int h, int q0)
{
    float* Ks = sm;
    float* Vs = sm + 2 * 64 * KS_STR;
    float* Ps = sm + 2 * 64 * KS_STR + 2 * 64 * VS_STR;

    int tid = threadIdx.x, lane = tid & 31, wid = tid >> 5;
    int gq = lane >> 2, gt = lane & 3;

    int wrow = wid * 16;
    int r1 = q0 + wrow + gq;
    int r2 = r1 + 8;
    bool r1ok = r1 < PN, r2ok = r2 < PN;

    const float* qkv_bh = qkv + ((size_t)b * PN) * 3072 + h * 64;

    {
        for (int i = tid; i < 64 * 16; i += 256) {
            int kr = i >> 4, dg = (i & 15) << 2;
            int gk = kr;
            int ok = (gk < PN) ? 16 : 0;
            const float* base = qkv_bh + (size_t)((gk < PN) ? gk : (PN - 1)) * 3072 + dg;
            cp_async16(&Ks[kr * KS_STR + dg], base + 1024, ok);
            cp_async16(&Vs[kr * VS_STR + dg], base + 2048, ok);
        }
        cp_commit();
    }

    unsigned qf[8][4];
    {
        const float* q1 = qkv_bh + (size_t)(r1ok ? r1 : 0) * 3072;
        const float* q2 = qkv_bh + (size_t)(r2ok ? r2 : 0) * 3072;
        #pragma unroll
        for (int ks = 0; ks < 8; ks++) {
            int c0 = ks * 8 + gt, c1 = c0 + 4;
            qf[ks][0] = r1ok ? __float_as_uint(to_tf32(__ldg(q1 + c0) * 0.125f)) : 0u;
            qf[ks][1] = r2ok ? __float_as_uint(to_tf32(__ldg(q2 + c0) * 0.125f)) : 0u;
            qf[ks][2] = r1ok ? __float_as_uint(to_tf32(__ldg(q1 + c1) * 0.125f)) : 0u;
            qf[ks][3] = r2ok ? __float_as_uint(to_tf32(__ldg(q2 + c1) * 0.125f)) : 0u;
        }
    }

    float oacc[8][4];
    #pragma unroll
    for (int nt = 0; nt < 8; nt++)
        #pragma unroll
        for (int c = 0; c < 4; c++) oacc[nt][c] = 0.f;
    float m1 = -1e30f, m2 = -1e30f, l1 = 0.f, l2 = 0.f;

    const float* bb1 = Bbias + (size_t)(r1ok ? r1 : 0) * PN;
    const float* bb2 = Bbias + (size_t)(r2ok ? r2 : 0) * PN;

    for (int it = 0; it < NKT; it++) {
        int k0 = it * 64;
        cp_wait<0>();
        __syncthreads();

        if (it + 1 < NKT) {
            int s = (it + 1) & 1;
            int nk0 = (it + 1) * 64;
            for (int i = tid; i < 64 * 16; i += 256) {
                int kr = i >> 4, dg = (i & 15) << 2;
                int gk = nk0 + kr;
                int ok = (gk < PN) ? 16 : 0;
                const float* base = qkv_bh + (size_t)((gk < PN) ? gk : (PN - 1)) * 3072 + dg;
                cp_async16(&Ks[(s * 64 + kr) * KS_STR + dg], base + 1024, ok);
                cp_async16(&Vs[(s * 64 + kr) * VS_STR + dg], base + 2048, ok);
            }
        }
        cp_commit();

        const float* Ksb = Ks + (it & 1) * 64 * KS_STR;
        const float* Vsb = Vs + (it & 1) * 64 * VS_STR;

        float sacc[8][4];
        #pragma unroll
        for (int nt = 0; nt < 8; nt++)
            #pragma unroll
            for (int c = 0; c < 4; c++) sacc[nt][c] = 0.f;

        #pragma unroll
        for (int ks = 0; ks < 8; ks++) {
            int kk = ks * 8;
            #pragma unroll
            for (int nt = 0; nt < 8; nt++) {
                unsigned b0 = __float_as_uint(Ksb[(nt * 8 + gq) * KS_STR + kk + gt]);
                unsigned b1 = __float_as_uint(Ksb[(nt * 8 + gq) * KS_STR + kk + gt + 4]);
                MMA_TF32(sacc[nt], qf[ks][0], qf[ks][1], qf[ks][2], qf[ks][3], b0, b1);
            }
        }

        float mx1 = -1e30f, mx2 = -1e30f;
        #pragma unroll
        for (int nt = 0; nt < 8; nt++) {
            int gc0 = k0 + nt * 8 + gt * 2;
            int gc1 = gc0 + 1;
            bool c0ok = gc0 < PN, c1ok = gc1 < PN;
            sacc[nt][0] = (r1ok && c0ok) ? sacc[nt][0] + __ldg(bb1 + gc0) : -1e30f;
            sacc[nt][1] = (r1ok && c1ok) ? sacc[nt][1] + __ldg(bb1 + gc1) : -1e30f;
            sacc[nt][2] = (r2ok && c0ok) ? sacc[nt][2] + __ldg(bb2 + gc0) : -1e30f;
            sacc[nt][3] = (r2ok && c1ok) ? sacc[nt][3] + __ldg(bb2 + gc1) : -1e30f;
            mx1 = fmaxf(mx1, fmaxf(sacc[nt][0], sacc[nt][1]));
            mx2 = fmaxf(mx2, fmaxf(sacc[nt][2], sacc[nt][3]));
        }
        mx1 = fmaxf(mx1, __shfl_xor_sync(0xffffffffu, mx1, 1));
        mx1 = fmaxf(mx1, __shfl_xor_sync(0xffffffffu, mx1, 2));
        mx2 = fmaxf(mx2, __shfl_xor_sync(0xffffffffu, mx2, 1));
        mx2 = fmaxf(mx2, __shfl_xor_sync(0xffffffffu, mx2, 2));

        float mn1 = fmaxf(m1, mx1), mn2 = fmaxf(m2, mx2);
        float corr1 = __expf(m1 - mn1), corr2 = __expf(m2 - mn2);
        m1 = mn1; m2 = mn2;

        float sum1 = 0.f, sum2 = 0.f;
        #pragma unroll
        for (int nt = 0; nt < 8; nt++) {
            float p0 = __expf(sacc[nt][0] - m1);
            float p1 = __expf(sacc[nt][1] - m1);
            float p2 = __expf(sacc[nt][2] - m2);
            float p3 = __expf(sacc[nt][3] - m2);
            sum1 += p0 + p1; sum2 += p2 + p3;
            int col = nt * 8 + gt * 2;
            *(float2*)&Ps[(wrow + gq)     * PS_STR + col] = make_float2(to_tf32(p0), to_tf32(p1));
            *(float2*)&Ps[(wrow + gq + 8) * PS_STR + col] = make_float2(to_tf32(p2), to_tf32(p3));
        }
        sum1 += __shfl_xor_sync(0xffffffffu, sum1, 1);
        sum1 += __shfl_xor_sync(0xffffffffu, sum1, 2);
        sum2 += __shfl_xor_sync(0xffffffffu, sum2, 1);
        sum2 += __shfl_xor_sync(0xffffffffu, sum2, 2);
        l1 = l1 * corr1 + sum1;
        l2 = l2 * corr2 + sum2;

        #pragma unroll
        for (int nt = 0; nt < 8; nt++) {
            oacc[nt][0] *= corr1; oacc[nt][1] *= corr1;
            oacc[nt][2] *= corr2; oacc[nt][3] *= corr2;
        }
        __syncwarp();

        #pragma unroll
        for (int ks = 0; ks < 8; ks++) {
            int kk = ks * 8;
            unsigned a0 = __float_as_uint(Ps[(wrow + gq)     * PS_STR + kk + gt]);
            unsigned a1 = __float_as_uint(Ps[(wrow + gq + 8) * PS_STR + kk + gt]);
            unsigned a2 = __float_as_uint(Ps[(wrow + gq)     * PS_STR + kk + gt + 4]);
            unsigned a3 = __float_as_uint(Ps[(wrow + gq + 8) * PS_STR + kk + gt + 4]);
            #pragma unroll
            for (int nt = 0; nt < 8; nt++) {
                unsigned b0 = __float_as_uint(Vsb[(kk + gt)     * VS_STR + nt * 8 + gq]);
                unsigned b1 = __float_as_uint(Vsb[(kk + gt + 4) * VS_STR + nt * 8 + gq]);
                MMA_TF32(oacc[nt], a0, a1, a2, a3, b0, b1);
            }
        }
    }

    float inv1 = 1.f / l1, inv2 = 1.f / l2;
    #pragma unroll
    for (int nt = 0; nt < 8; nt++) {
        int col = h * 64 + nt * 8 + gt * 2;
        if (r1ok) {
            float* dst = y + ((size_t)(b * PN + r1)) * PD + col;
            dst[0] = oacc[nt][0] * inv1;
            dst[1] = oacc[nt][1] * inv1;
        }
        if (r2ok) {
            float* dst = y + ((size_t)(b * PN + r2)) * PD + col;
            dst[0] = oacc[nt][2] * inv2;
            dst[1] = oacc[nt][3] * inv2;
        }
    }
}

// ---------------------------------------------------------------------------
// Combined kernel: blocks [0,1152) = flash; rest = gate GEMM (128x128 tiles)
// ---------------------------------------------------------------------------
#define FLASH_BLOCKS (((PN + 127) / 128) * PH * PB)    // 1152
#define GATE_NX (PD / 128)                             // 8
#define GATE_BLOCKS (GATE_NX * ((PM + 127) / 128))     // 8*65 = 520

__global__ __launch_bounds__(256, 2) void flash_gate_kernel(
    const float* __restrict__ qkv, const float* __restrict__ Bbias,
    float* __restrict__ y,
    const float* __restrict__ h, const float* __restrict__ gate_w,
    const float* __restrict__ gate_b, float* __restrict__ sig)
{
    extern __shared__ char smraw[];
    int bid = blockIdx.x;
    if (bid < FLASH_BLOCKS) {
        int qt = bid % 9;
        int hh = (bid / 9) % PH;
        int bb = bid / (9 * PH);
        flash_body((float*)smraw, qkv, Bbias, y, bb, hh, qt * 128);
    } else {
        int gid = bid - FLASH_BLOCKS;
        int n0 = (gid % GATE_NX) * 128;
        int m0 = (gid / GATE_NX) * 128;
        gemm_body<4>(smraw, m0, n0, h, gate_w, gate_b, sig,
                     PM, PD, PD, nullptr, nullptr, nullptr);
    }
}

// ---------------------------------------------------------------------------
// Launch
// ---------------------------------------------------------------------------
extern "C" void kernel_launch(void* const* d_in, const int* in_sizes, int n_in,
                              void* d_out, int out_size)
{
    (void)in_sizes; (void)n_in; (void)out_size;
    const float* x      = (const float*)d_in[0];
    const float* fc     = (const float*)d_in[1];
    const float* g      = (const float*)d_in[2];
    const float* qkv_w  = (const float*)d_in[3];
    const float* qkv_b  = (const float*)d_in[4];
    const float* out_w  = (const float*)d_in[5];
    const float* out_b  = (const float*)d_in[6];
    const float* gate_w = (const float*)d_in[7];
    const float* gate_b = (const float*)d_in[8];
    const float* Bbias  = (const float*)d_in[9];
    float* out = (float*)d_out;

    float *h, *qkv, *y, *sig;
    cudaGetSymbolAddress((void**)&h,   g_h);
    cudaGetSymbolAddress((void**)&qkv, g_qkv);
    cudaGetSymbolAddress((void**)&y,   g_y);
    cudaGetSymbolAddress((void**)&sig, g_sig);

    cudaFuncSetAttribute(mma_nt<2>, cudaFuncAttributeMaxDynamicSharedMemorySize, GEMM_SMEM);
    cudaFuncSetAttribute(mma_nt<3>, cudaFuncAttributeMaxDynamicSharedMemorySize, GEMM_SMEM);
    cudaFuncSetAttribute(flash_gate_kernel,
                         cudaFuncAttributeMaxDynamicSharedMemorySize, FLASH_SMEM);

    // 1. zero-centered RMSNorm (fp32)
    rmsnorm_kernel<<<PM, 256>>>(x, g, h);

    // 2. QKV projection with fused RoPE epilogue (128x128 tiles)
    dim3 g1(3072 / 128, (PM + 127) / 128);
    mma_nt<2><<<g1, 256, GEMM_SMEM>>>(h, qkv_w, qkv_b, qkv, PM, 3072, PD,
                                      nullptr, nullptr, fc);

    // 3. flash attention + gate GEMM fused into one launch (overlap)
    flash_gate_kernel<<<FLASH_BLOCKS + GATE_BLOCKS, 256, FLASH_SMEM>>>(
        qkv, Bbias, y, h, gate_w, gate_b, sig);

    // 4. out projection with final fused epilogue:
    //    out = x + sig * (y @ out_w^T + out_b)
    dim3 g2(PD / 128, (PM + 127) / 128);
    mma_nt<3><<<g2, 256, GEMM_SMEM>>>(y, out_w, out_b, out, PM, PD, PD,
                                      x, sig, nullptr);
}